// round 9
// baseline (speedup 1.0000x reference)
#include <cuda_runtime.h>
#include <cuda_bf16.h>
#include <cstdint>

constexpr int M = 1024;
constexpr int N = 32768;
constexpr int K = 512;
constexpr float MARGIN = 0.3f;

constexpr int BM = 128, BN = 256, BK = 32;
constexpr int NCH = K / BK;              // 16
constexpr int NSTAGE = 3;
constexpr int ROWB = 80;                 // 64B bf16 data + 16B pad per k-chunk row

// dynamic smem layout (triple buffered)
constexpr uint32_t OFF_LAB = 0;                          // 256 ints = 1KB
constexpr uint32_t OFF_A   = 1024;
constexpr uint32_t A_STAGE = BM * ROWB;                  // 10240
constexpr uint32_t OFF_B   = OFF_A + NSTAGE * A_STAGE;   // 31744
constexpr uint32_t B_STAGE = BN * ROWB;                  // 20480
constexpr uint32_t SMEM_TOTAL = OFF_B + NSTAGE * B_STAGE;   // 93184

// per-row results, ordered-uint encoding (min-float == min-uint)
__device__ unsigned g_posU[M];
__device__ unsigned g_negU[M];
__device__ unsigned g_ctr;               // CTA completion counter (self-resetting)

__device__ __forceinline__ float f_inf()  { return __int_as_float(0x7f800000); }
__device__ __forceinline__ float f_ninf() { return __int_as_float(0xff800000); }

__device__ __forceinline__ unsigned encOrd(float f) {
    unsigned b = __float_as_uint(f);
    return (b & 0x80000000u) ? ~b : (b | 0x80000000u);
}
__device__ __forceinline__ float decOrd(unsigned u) {
    return (u & 0x80000000u) ? __uint_as_float(u ^ 0x80000000u)
                             : __uint_as_float(~u);
}

__device__ __forceinline__ uint32_t smem_u32(const void* p) {
    uint32_t a;
    asm("{ .reg .u64 t; cvta.to.shared.u64 t, %1; cvt.u32.u64 %0, t; }" : "=r"(a) : "l"(p));
    return a;
}
__device__ __forceinline__ void ldsm_x4(uint32_t* r, uint32_t addr) {
    asm volatile("ldmatrix.sync.aligned.m8n8.x4.shared.b16 {%0,%1,%2,%3}, [%4];"
                 : "=r"(r[0]), "=r"(r[1]), "=r"(r[2]), "=r"(r[3]) : "r"(addr));
}
__device__ __forceinline__ void mma_bf16(float* d, const uint32_t* a, const uint32_t* b) {
    asm volatile(
        "mma.sync.aligned.m16n8k16.row.col.f32.bf16.bf16.f32 "
        "{%0,%1,%2,%3}, {%4,%5,%6,%7}, {%8,%9}, {%0,%1,%2,%3};"
        : "+f"(d[0]), "+f"(d[1]), "+f"(d[2]), "+f"(d[3])
        : "r"(a[0]), "r"(a[1]), "r"(a[2]), "r"(a[3]), "r"(b[0]), "r"(b[1]));
}
__device__ __forceinline__ void sts64_bf16(uint32_t addr, float4 v) {
    __nv_bfloat162 lo = __float22bfloat162_rn(make_float2(v.x, v.y));
    __nv_bfloat162 hi = __float22bfloat162_rn(make_float2(v.z, v.w));
    asm volatile("st.shared.v2.u32 [%0], {%1, %2};"
                 :: "r"(addr), "r"(*(uint32_t*)&lo), "r"(*(uint32_t*)&hi));
}

__global__ __launch_bounds__(512, 1)
void tl_gemm(const float* __restrict__ A, const float* __restrict__ B,
             const int* __restrict__ targets, const int* __restrict__ idxv,
             const int* __restrict__ labels, float* __restrict__ out)
{
    extern __shared__ __align__(128) char smem[];
    __shared__ int      sT[BM];
    __shared__ int      sI[BM];
    __shared__ unsigned sPosU[BM];
    __shared__ unsigned sNegU[BM];
    __shared__ float    sRed[16];
    __shared__ unsigned sIsLast;

    const uint32_t sb = smem_u32(smem);
    const uint32_t sA = sb + OFF_A;
    const uint32_t sB = sb + OFF_B;
    int* sLab = (int*)(smem + OFF_LAB);

    const int tid  = threadIdx.x;
    const int lane = tid & 31;
    const int wid  = tid >> 5;
    const int rowBase = blockIdx.y * BM;
    const int colBase = blockIdx.x * BN;

    // 16 warps: 4 (m) x 4 (n); warp tile 32 x 64
    const int warp_m = (wid >> 2) * 32;
    const int warp_n = (wid & 3) * 64;

    for (int i = tid; i < BN; i += 512) sLab[i] = labels[colBase + i];
    if (tid < BM) {
        sT[tid] = targets[rowBase + tid];
        sI[tid] = idxv[rowBase + tid];
        sPosU[tid] = 0xFFFFFFFFu;
        sNegU[tid] = 0u;
    }

    // fp32 loader with inline bf16 conversion.
    float4 rA[2], rB[4];
    auto ldg_stage = [&](int c) {
        const int kb = c * BK;
#pragma unroll
        for (int i = 0; i < 2; ++i) {
            const int v = tid + i * 512;
            const int r = v >> 3, q = v & 7;
            rA[i] = *reinterpret_cast<const float4*>(
                &A[(size_t)(rowBase + r) * K + kb + q * 4]);
        }
#pragma unroll
        for (int i = 0; i < 4; ++i) {
            const int v = tid + i * 512;
            const int r = v >> 3, q = v & 7;
            rB[i] = *reinterpret_cast<const float4*>(
                &B[(size_t)(colBase + r) * K + kb + q * 4]);
        }
    };
    auto sts_stage = [&](int st) {
        const uint32_t dA = sA + st * A_STAGE;
        const uint32_t dB = sB + st * B_STAGE;
#pragma unroll
        for (int i = 0; i < 2; ++i) {
            const int v = tid + i * 512;
            const int r = v >> 3, q = v & 7;
            sts64_bf16(dA + r * ROWB + q * 8, rA[i]);
        }
#pragma unroll
        for (int i = 0; i < 4; ++i) {
            const int v = tid + i * 512;
            const int r = v >> 3, q = v & 7;
            sts64_bf16(dB + r * ROWB + q * 8, rB[i]);
        }
    };

    // ldmatrix lane offsets
    const uint32_t aOff = (uint32_t)(warp_m + (lane & 15)) * ROWB + (lane >> 4) * 16;
    const uint32_t bOff = (uint32_t)(warp_n + (lane & 7) + ((lane >> 4) & 1) * 8) * ROWB
                        + ((lane >> 3) & 1) * 16;

    float acc[2][8][4] = {};

    // Prologue: stage chunk 0, preload chunk 1 into registers.
    ldg_stage(0);
    sts_stage(0);
    ldg_stage(1);
    __syncthreads();

#pragma unroll 1
    for (int c = 0; c < NCH; ++c) {
        // STS for chunk c+1 issues BEFORE this chunk's MMAs -> drained by barrier time.
        if (c + 1 < NCH) sts_stage((c + 1) % NSTAGE);
        if (c + 2 < NCH) ldg_stage(c + 2);

        const uint32_t stA = sA + (c % NSTAGE) * A_STAGE;
        const uint32_t stB = sB + (c % NSTAGE) * B_STAGE;
#pragma unroll
        for (int ks = 0; ks < 2; ++ks) {
            uint32_t af[2][4], bfr[4][4];
#pragma unroll
            for (int mi = 0; mi < 2; ++mi)
                ldsm_x4(af[mi], stA + aOff + mi * 16 * ROWB + ks * 32);
#pragma unroll
            for (int g = 0; g < 4; ++g)
                ldsm_x4(bfr[g], stB + bOff + g * 16 * ROWB + ks * 32);
#pragma unroll
            for (int mi = 0; mi < 2; ++mi)
#pragma unroll
                for (int ni = 0; ni < 8; ++ni)
                    mma_bf16(acc[mi][ni], af[mi], &bfr[ni >> 1][(ni & 1) * 2]);
        }
        __syncthreads();
    }

    // Epilogue: masked min/max with ordered-uint atomics.
    const int lq = lane >> 2;
    const int lr = (lane & 3) * 2;
#pragma unroll
    for (int mi = 0; mi < 2; ++mi) {
#pragma unroll
        for (int h = 0; h < 2; ++h) {
            const int rloc = warp_m + mi * 16 + h * 8 + lq;
            const int tg = sT[rloc];
            const int ix = sI[rloc];
            float pmin = f_inf(), nmax = f_ninf();
#pragma unroll
            for (int ni = 0; ni < 8; ++ni) {
#pragma unroll
                for (int j = 0; j < 2; ++j) {
                    const int cloc = warp_n + ni * 8 + lr + j;
                    const float v = acc[mi][ni][h * 2 + j];
                    if (sLab[cloc] == tg) {
                        if (colBase + cloc != ix) pmin = fminf(pmin, v);
                    } else {
                        nmax = fmaxf(nmax, v);
                    }
                }
            }
            if (pmin <  f_inf())  atomicMin(&sPosU[rloc], encOrd(pmin));
            if (nmax > f_ninf())  atomicMax(&sNegU[rloc], encOrd(nmax));
        }
    }
    __syncthreads();

    if (tid < BM) {
        const unsigned p = sPosU[tid], q = sNegU[tid];
        if (p != 0xFFFFFFFFu) atomicMin(&g_posU[rowBase + tid], p);
        if (q != 0u)          atomicMax(&g_negU[rowBase + tid], q);
    }

    // ---- fused finale: last CTA to finish computes the mean loss ----
    __threadfence();
    if (tid == 0) {
        const unsigned total = gridDim.x * gridDim.y;
        sIsLast = (atomicAdd(&g_ctr, 1u) == total - 1u);
    }
    __syncthreads();
    if (!sIsLast) return;

    __threadfence();   // acquire: see all CTAs' atomics
    float l = 0.f;
#pragma unroll
    for (int r = 0; r < 2; ++r) {
        const int row = tid + r * 512;
        const float pos = decOrd(__ldcg(&g_posU[row]));
        const float neg = decOrd(__ldcg(&g_negU[row]));
        l += fmaxf(neg - pos + MARGIN, 0.0f);
    }
#pragma unroll
    for (int o = 16; o > 0; o >>= 1) l += __shfl_xor_sync(0xffffffffu, l, o);
    if (lane == 0) sRed[wid] = l;
    __syncthreads();
    if (tid < 16) {
        float s = sRed[tid];
#pragma unroll
        for (int o = 8; o > 0; o >>= 1) s += __shfl_xor_sync(0xffffu, s, o);
        if (tid == 0) {
            out[0] = s * (1.0f / (float)M);
            g_ctr = 0;                    // reset for next graph replay
        }
    }
}

extern "C" void kernel_launch(void* const* d_in, const int* in_sizes, int n_in,
                              void* d_out, int out_size) {
    const float* A       = (const float*)d_in[0];
    const float* B       = (const float*)d_in[1];
    const int*   targets = (const int*)  d_in[2];
    const int*   idxv    = (const int*)  d_in[3];
    const int*   labels  = (const int*)  d_in[4];
    float*       out     = (float*)d_out;

    static bool attrSet = false;
    if (!attrSet) {
        cudaFuncSetAttribute(tl_gemm, cudaFuncAttributeMaxDynamicSharedMemorySize,
                             SMEM_TOTAL);
        attrSet = true;
    }

    void *pPos = nullptr, *pNeg = nullptr;
    cudaGetSymbolAddress(&pPos, g_posU);
    cudaGetSymbolAddress(&pNeg, g_negU);
    cudaMemsetAsync(pPos, 0xFF, M * sizeof(unsigned));   // min-identity
    cudaMemsetAsync(pNeg, 0x00, M * sizeof(unsigned));   // max-identity

    dim3 grid(N / BN, M / BM);   // 128 x 8 = 1024 CTAs
    tl_gemm<<<grid, 512, SMEM_TOTAL>>>(A, B, targets, idxv, labels, out);
}

// round 10
// speedup vs baseline: 1.2434x; 1.2434x over previous
#include <cuda_runtime.h>
#include <cuda_bf16.h>
#include <cuda_fp16.h>
#include <cstdint>

constexpr int M = 1024;
constexpr int N = 32768;
constexpr int K = 512;
constexpr float MARGIN = 0.3f;

constexpr int BM = 128, BN = 256, BK = 32;
constexpr int NCH = K / BK;              // 16
constexpr int NSTAGE = 3;
constexpr int ROWB = 80;                 // 64B bf16 data + 16B pad per k-chunk row

// dynamic smem layout
constexpr uint32_t OFF_LAB = 0;                          // 256 ints = 1KB
constexpr uint32_t OFF_A   = 1024;
constexpr uint32_t A_STAGE = BM * ROWB;                  // 10240
constexpr uint32_t OFF_B   = OFF_A + NSTAGE * A_STAGE;   // 31744
constexpr uint32_t B_STAGE = BN * ROWB;                  // 20480
constexpr uint32_t SMEM_TOTAL = OFF_B + NSTAGE * B_STAGE;   // 93184 (x2 CTAs = 182KB/SM)

__device__ unsigned g_posU[M];
__device__ unsigned g_negU[M];
__device__ unsigned g_ctr;
__device__ __nv_bfloat16 g_Ab[M * K];
__device__ __nv_bfloat16 g_Bb[(size_t)N * K];

__device__ __forceinline__ float f_inf()  { return __int_as_float(0x7f800000); }
__device__ __forceinline__ float f_ninf() { return __int_as_float(0xff800000); }

__device__ __forceinline__ unsigned encOrd(float f) {
    unsigned b = __float_as_uint(f);
    return (b & 0x80000000u) ? ~b : (b | 0x80000000u);
}
__device__ __forceinline__ float decOrd(unsigned u) {
    return (u & 0x80000000u) ? __uint_as_float(u ^ 0x80000000u)
                             : __uint_as_float(~u);
}

__device__ __forceinline__ uint32_t smem_u32(const void* p) {
    uint32_t a;
    asm("{ .reg .u64 t; cvta.to.shared.u64 t, %1; cvt.u32.u64 %0, t; }" : "=r"(a) : "l"(p));
    return a;
}
__device__ __forceinline__ void ldsm_x4(uint32_t* r, uint32_t addr) {
    asm volatile("ldmatrix.sync.aligned.m8n8.x4.shared.b16 {%0,%1,%2,%3}, [%4];"
                 : "=r"(r[0]), "=r"(r[1]), "=r"(r[2]), "=r"(r[3]) : "r"(addr));
}
// bf16 inputs, f16 accumulators are not a valid combo; use f16 inputs + f16 acc.
__device__ __forceinline__ void mma_f16(uint32_t* d, const uint32_t* a, const uint32_t* b) {
    asm volatile(
        "mma.sync.aligned.m16n8k16.row.col.f16.f16.f16.f16 "
        "{%0,%1}, {%2,%3,%4,%5}, {%6,%7}, {%0,%1};"
        : "+r"(d[0]), "+r"(d[1])
        : "r"(a[0]), "r"(a[1]), "r"(a[2]), "r"(a[3]), "r"(b[0]), "r"(b[1]));
}
__device__ __forceinline__ void cp_async16(uint32_t dst, const void* src) {
    asm volatile("cp.async.cg.shared.global [%0], [%1], 16;" :: "r"(dst), "l"(src));
}
__device__ __forceinline__ void cp_commit() {
    asm volatile("cp.async.commit_group;" ::: "memory");
}
template <int NG> __device__ __forceinline__ void cp_wait() {
    asm volatile("cp.async.wait_group %0;" :: "n"(NG) : "memory");
}

// fp32 -> f16 scratch (f16 inputs pair with f16 accumulators; R7 validated precision)
__global__ void tl_quant(const float* __restrict__ A, const float* __restrict__ B) {
    const int gid = blockIdx.x * blockDim.x + threadIdx.x;
    const int nth = gridDim.x * blockDim.x;
    __half* Ah = reinterpret_cast<__half*>(g_Ab);
    __half* Bh = reinterpret_cast<__half*>(g_Bb);
    for (int i = gid; i < M * K / 4; i += nth) {
        float4 v = *reinterpret_cast<const float4*>(A + (size_t)i * 4);
        __half2 lo = __floats2half2_rn(v.x, v.y);
        __half2 hi = __floats2half2_rn(v.z, v.w);
        *reinterpret_cast<uint2*>(Ah + (size_t)i * 4) =
            make_uint2(*(uint32_t*)&lo, *(uint32_t*)&hi);
    }
    for (size_t i = gid; i < (size_t)N * K / 4; i += nth) {
        float4 v = *reinterpret_cast<const float4*>(B + i * 4);
        __half2 lo = __floats2half2_rn(v.x, v.y);
        __half2 hi = __floats2half2_rn(v.z, v.w);
        *reinterpret_cast<uint2*>(Bh + i * 4) =
            make_uint2(*(uint32_t*)&lo, *(uint32_t*)&hi);
    }
}

__global__ __launch_bounds__(256, 2)
void tl_gemm(const int* __restrict__ targets, const int* __restrict__ idxv,
             const int* __restrict__ labels, float* __restrict__ out)
{
    extern __shared__ __align__(128) char smem[];
    __shared__ int      sT[BM];
    __shared__ int      sI[BM];
    __shared__ unsigned sPosU[BM];
    __shared__ unsigned sNegU[BM];
    __shared__ float    sRed[8];
    __shared__ unsigned sIsLast;

    const uint32_t sb = smem_u32(smem);
    const uint32_t sA = sb + OFF_A;
    const uint32_t sB = sb + OFF_B;
    int* sLab = (int*)(smem + OFF_LAB);

    const int tid  = threadIdx.x;
    const int lane = tid & 31;
    const int wid  = tid >> 5;
    const int rowBase = blockIdx.y * BM;
    const int colBase = blockIdx.x * BN;

    // 8 warps: 2 (m) x 4 (n); warp tile 64 x 64
    const int warp_m = (wid >> 2) * 64;
    const int warp_n = (wid & 3) * 64;

    const __half* Ah = reinterpret_cast<const __half*>(g_Ab);
    const __half* Bh = reinterpret_cast<const __half*>(g_Bb);

    for (int i = tid; i < BN; i += 256) sLab[i] = labels[colBase + i];
    if (tid < BM) {
        sT[tid] = targets[rowBase + tid];
        sI[tid] = idxv[rowBase + tid];
        sPosU[tid] = 0xFFFFFFFFu;
        sNegU[tid] = 0u;
    }

    // cp.async stage loader: A 512 x 16B (2/thread), B 1024 x 16B (4/thread)
    auto load_stage = [&](int st, int c) {
        const int kb = c * BK;
        const uint32_t dA = sA + st * A_STAGE;
        const uint32_t dB = sB + st * B_STAGE;
#pragma unroll
        for (int i = 0; i < 2; ++i) {
            const int v = tid + i * 256;
            const int r = v >> 2, q = v & 3;
            cp_async16(dA + r * ROWB + q * 16,
                       Ah + (size_t)(rowBase + r) * K + kb + q * 8);
        }
#pragma unroll
        for (int i = 0; i < 4; ++i) {
            const int v = tid + i * 256;
            const int r = v >> 2, q = v & 3;
            cp_async16(dB + r * ROWB + q * 16,
                       Bh + (size_t)(colBase + r) * K + kb + q * 8);
        }
        cp_commit();
    };

    // ldmatrix lane offsets
    const uint32_t aOff = (uint32_t)(warp_m + (lane & 15)) * ROWB + (lane >> 4) * 16;
    const uint32_t bOff = (uint32_t)(warp_n + (lane & 7) + ((lane >> 4) & 1) * 8) * ROWB
                        + ((lane >> 3) & 1) * 16;

    uint32_t acc[4][8][2] = {};   // f16x2 accumulators: [mi][ni][row-half]

    load_stage(0, 0);
    load_stage(1, 1);

#pragma unroll 1
    for (int c = 0; c < NCH; ++c) {
        if (c + 1 < NCH) cp_wait<1>(); else cp_wait<0>();
        __syncthreads();
        if (c + 2 < NCH) load_stage((c + 2) % NSTAGE, c + 2);

        const uint32_t stA = sA + (c % NSTAGE) * A_STAGE;
        const uint32_t stB = sB + (c % NSTAGE) * B_STAGE;
#pragma unroll
        for (int ks = 0; ks < 2; ++ks) {
            uint32_t af[4][4], bfr[4][4];
#pragma unroll
            for (int mi = 0; mi < 4; ++mi)
                ldsm_x4(af[mi], stA + aOff + mi * 16 * ROWB + ks * 32);
#pragma unroll
            for (int g = 0; g < 4; ++g)
                ldsm_x4(bfr[g], stB + bOff + g * 16 * ROWB + ks * 32);
#pragma unroll
            for (int mi = 0; mi < 4; ++mi)
#pragma unroll
                for (int ni = 0; ni < 8; ++ni)
                    mma_f16(acc[mi][ni], af[mi], &bfr[ni >> 1][(ni & 1) * 2]);
        }
        __syncthreads();
    }

    // Epilogue: unpack f16 acc, masked min/max with ordered-uint atomics.
    const int lq = lane >> 2;
    const int lr = (lane & 3) * 2;
#pragma unroll
    for (int mi = 0; mi < 4; ++mi) {
#pragma unroll
        for (int h = 0; h < 2; ++h) {
            const int rloc = warp_m + mi * 16 + h * 8 + lq;
            const int tg = sT[rloc];
            const int ix = sI[rloc];
            float pmin = f_inf(), nmax = f_ninf();
#pragma unroll
            for (int ni = 0; ni < 8; ++ni) {
                const float2 f2 = __half22float2(
                    *reinterpret_cast<const __half2*>(&acc[mi][ni][h]));
#pragma unroll
                for (int j = 0; j < 2; ++j) {
                    const int cloc = warp_n + ni * 8 + lr + j;
                    const float v = (j == 0) ? f2.x : f2.y;
                    if (sLab[cloc] == tg) {
                        if (colBase + cloc != ix) pmin = fminf(pmin, v);
                    } else {
                        nmax = fmaxf(nmax, v);
                    }
                }
            }
            if (pmin <  f_inf())  atomicMin(&sPosU[rloc], encOrd(pmin));
            if (nmax > f_ninf())  atomicMax(&sNegU[rloc], encOrd(nmax));
        }
    }
    __syncthreads();

    if (tid < BM) {
        const unsigned p = sPosU[tid], q = sNegU[tid];
        if (p != 0xFFFFFFFFu) atomicMin(&g_posU[rowBase + tid], p);
        if (q != 0u)          atomicMax(&g_negU[rowBase + tid], q);
    }

    // ---- fused finale ----
    __threadfence();
    if (tid == 0) {
        const unsigned total = gridDim.x * gridDim.y;
        sIsLast = (atomicAdd(&g_ctr, 1u) == total - 1u);
    }
    __syncthreads();
    if (!sIsLast) return;

    __threadfence();
    float l = 0.f;
#pragma unroll
    for (int r = 0; r < 4; ++r) {
        const int row = tid + r * 256;
        const float pos = decOrd(__ldcg(&g_posU[row]));
        const float neg = decOrd(__ldcg(&g_negU[row]));
        l += fmaxf(neg - pos + MARGIN, 0.0f);
    }
#pragma unroll
    for (int o = 16; o > 0; o >>= 1) l += __shfl_xor_sync(0xffffffffu, l, o);
    if (lane == 0) sRed[wid] = l;
    __syncthreads();
    if (tid < 8) {
        float s = sRed[tid];
#pragma unroll
        for (int o = 4; o > 0; o >>= 1) s += __shfl_xor_sync(0xffu, s, o);
        if (tid == 0) {
            out[0] = s * (1.0f / (float)M);
            g_ctr = 0;
        }
    }
}

extern "C" void kernel_launch(void* const* d_in, const int* in_sizes, int n_in,
                              void* d_out, int out_size) {
    const float* A       = (const float*)d_in[0];
    const float* B       = (const float*)d_in[1];
    const int*   targets = (const int*)  d_in[2];
    const int*   idxv    = (const int*)  d_in[3];
    const int*   labels  = (const int*)  d_in[4];
    float*       out     = (float*)d_out;

    static bool attrSet = false;
    if (!attrSet) {
        cudaFuncSetAttribute(tl_gemm, cudaFuncAttributeMaxDynamicSharedMemorySize,
                             SMEM_TOTAL);
        attrSet = true;
    }

    void *pPos = nullptr, *pNeg = nullptr;
    cudaGetSymbolAddress(&pPos, g_posU);
    cudaGetSymbolAddress(&pNeg, g_negU);
    cudaMemsetAsync(pPos, 0xFF, M * sizeof(unsigned));
    cudaMemsetAsync(pNeg, 0x00, M * sizeof(unsigned));

    tl_quant<<<1024, 256>>>(A, B);
    dim3 grid(N / BN, M / BM);   // 128 x 8 = 1024 CTAs
    tl_gemm<<<grid, 256, SMEM_TOTAL>>>(targets, idxv, labels, out);
}

// round 11
// speedup vs baseline: 1.4179x; 1.1404x over previous
#include <cuda_runtime.h>
#include <cuda_bf16.h>
#include <cuda_fp16.h>
#include <cstdint>

constexpr int M = 1024;
constexpr int N = 32768;
constexpr int K = 512;
constexpr float MARGIN = 0.3f;

constexpr int BM = 128, BN = 256, BK = 64;
constexpr int NCH = K / BK;              // 8
constexpr int ROWB = 128;                // 64 f16 = 128B row, SW128 swizzle (no pad)

// dynamic smem layout (double buffered, SW128)
constexpr uint32_t OFF_LAB = 0;                          // 256 ints = 1KB
constexpr uint32_t OFF_A   = 1024;
constexpr uint32_t A_STAGE = BM * ROWB;                  // 16384
constexpr uint32_t OFF_B   = OFF_A + 2 * A_STAGE;        // 33792
constexpr uint32_t B_STAGE = BN * ROWB;                  // 32768
constexpr uint32_t SMEM_TOTAL = OFF_B + 2 * B_STAGE;     // 99328 (x2 CTAs = 199KB/SM)

__device__ unsigned g_posU[M];
__device__ unsigned g_negU[M];
__device__ unsigned g_ctr;
__device__ __half g_Ah[M * K];
__device__ __half g_Bh[(size_t)N * K];

__device__ __forceinline__ float f_inf()  { return __int_as_float(0x7f800000); }
__device__ __forceinline__ float f_ninf() { return __int_as_float(0xff800000); }

__device__ __forceinline__ unsigned encOrd(float f) {
    unsigned b = __float_as_uint(f);
    return (b & 0x80000000u) ? ~b : (b | 0x80000000u);
}
__device__ __forceinline__ float decOrd(unsigned u) {
    return (u & 0x80000000u) ? __uint_as_float(u ^ 0x80000000u)
                             : __uint_as_float(~u);
}

__device__ __forceinline__ uint32_t swz(uint32_t b) { return b ^ ((b >> 3) & 0x70); }

__device__ __forceinline__ uint32_t smem_u32(const void* p) {
    uint32_t a;
    asm("{ .reg .u64 t; cvta.to.shared.u64 t, %1; cvt.u32.u64 %0, t; }" : "=r"(a) : "l"(p));
    return a;
}
__device__ __forceinline__ void ldsm_x4(uint32_t* r, uint32_t addr) {
    asm volatile("ldmatrix.sync.aligned.m8n8.x4.shared.b16 {%0,%1,%2,%3}, [%4];"
                 : "=r"(r[0]), "=r"(r[1]), "=r"(r[2]), "=r"(r[3]) : "r"(addr));
}
__device__ __forceinline__ void mma_f16(uint32_t* d, const uint32_t* a, const uint32_t* b) {
    asm volatile(
        "mma.sync.aligned.m16n8k16.row.col.f16.f16.f16.f16 "
        "{%0,%1}, {%2,%3,%4,%5}, {%6,%7}, {%0,%1};"
        : "+r"(d[0]), "+r"(d[1])
        : "r"(a[0]), "r"(a[1]), "r"(a[2]), "r"(a[3]), "r"(b[0]), "r"(b[1]));
}
__device__ __forceinline__ void cp_async16(uint32_t dst, const void* src) {
    asm volatile("cp.async.cg.shared.global [%0], [%1], 16;" :: "r"(dst), "l"(src));
}
__device__ __forceinline__ void cp_commit() {
    asm volatile("cp.async.commit_group;" ::: "memory");
}
template <int NG> __device__ __forceinline__ void cp_wait() {
    asm volatile("cp.async.wait_group %0;" :: "n"(NG) : "memory");
}

// fp32 -> f16 scratch
__global__ void tl_quant(const float* __restrict__ A, const float* __restrict__ B) {
    const int gid = blockIdx.x * blockDim.x + threadIdx.x;
    const int nth = gridDim.x * blockDim.x;
    for (int i = gid; i < M * K / 4; i += nth) {
        float4 v = *reinterpret_cast<const float4*>(A + (size_t)i * 4);
        __half2 lo = __floats2half2_rn(v.x, v.y);
        __half2 hi = __floats2half2_rn(v.z, v.w);
        *reinterpret_cast<uint2*>(g_Ah + (size_t)i * 4) =
            make_uint2(*(uint32_t*)&lo, *(uint32_t*)&hi);
    }
    for (size_t i = gid; i < (size_t)N * K / 4; i += nth) {
        float4 v = *reinterpret_cast<const float4*>(B + i * 4);
        __half2 lo = __floats2half2_rn(v.x, v.y);
        __half2 hi = __floats2half2_rn(v.z, v.w);
        *reinterpret_cast<uint2*>(g_Bh + i * 4) =
            make_uint2(*(uint32_t*)&lo, *(uint32_t*)&hi);
    }
}

__global__ __launch_bounds__(256, 2)
void tl_gemm(const int* __restrict__ targets, const int* __restrict__ idxv,
             const int* __restrict__ labels, float* __restrict__ out)
{
    extern __shared__ __align__(1024) char smem[];
    __shared__ int      sT[BM];
    __shared__ int      sI[BM];
    __shared__ unsigned sPosU[BM];
    __shared__ unsigned sNegU[BM];
    __shared__ float    sRed[8];
    __shared__ unsigned sIsLast;

    const uint32_t sb = smem_u32(smem);
    const uint32_t sA = sb + OFF_A;
    const uint32_t sB = sb + OFF_B;
    int* sLab = (int*)(smem + OFF_LAB);

    const int tid  = threadIdx.x;
    const int lane = tid & 31;
    const int wid  = tid >> 5;
    const int rowBase = blockIdx.y * BM;
    const int colBase = blockIdx.x * BN;

    // 8 warps: 2 (m) x 4 (n); warp tile 64 x 64
    const int warp_m = (wid >> 2) * 64;
    const int warp_n = (wid & 3) * 64;

    for (int i = tid; i < BN; i += 256) sLab[i] = labels[colBase + i];
    if (tid < BM) {
        sT[tid] = targets[rowBase + tid];
        sI[tid] = idxv[rowBase + tid];
        sPosU[tid] = 0xFFFFFFFFu;
        sNegU[tid] = 0u;
    }

    // stage loader (BK=64): A 128 rows x 8 chunks = 1024 (4/thread),
    //                       B 256 rows x 8 chunks = 2048 (8/thread)
    auto load_stage = [&](int st, int c) {
        const int kb = c * BK;
        const uint32_t dA = sA + st * A_STAGE;
        const uint32_t dB = sB + st * B_STAGE;
#pragma unroll
        for (int i = 0; i < 4; ++i) {
            const int v = tid + i * 256;
            const int r = v >> 3, q = v & 7;
            cp_async16(dA + swz((uint32_t)(r * ROWB + q * 16)),
                       g_Ah + (size_t)(rowBase + r) * K + kb + q * 8);
        }
#pragma unroll
        for (int i = 0; i < 8; ++i) {
            const int v = tid + i * 256;
            const int r = v >> 3, q = v & 7;
            cp_async16(dB + swz((uint32_t)(r * ROWB + q * 16)),
                       g_Bh + (size_t)(colBase + r) * K + kb + q * 8);
        }
        cp_commit();
    };

    // ldmatrix lane base offsets (unswizzled; swizzle applied per access)
    const uint32_t aRow = (uint32_t)(warp_m + (lane & 15));
    const uint32_t aCol = (lane >> 4) * 16;
    const uint32_t bRow = (uint32_t)(warp_n + (lane & 7) + ((lane >> 4) & 1) * 8);
    const uint32_t bCol = ((lane >> 3) & 1) * 16;

    uint32_t acc[4][8][2] = {};   // f16x2 accumulators

    load_stage(0, 0);
    load_stage(1, 1);

#pragma unroll 1
    for (int c = 0; c < NCH; ++c) {
        if (c + 1 < NCH) cp_wait<1>(); else cp_wait<0>();
        __syncthreads();

        const uint32_t stA = sA + (c & 1) * A_STAGE;
        const uint32_t stB = sB + (c & 1) * B_STAGE;
#pragma unroll
        for (int ks = 0; ks < 4; ++ks) {
            uint32_t af[4][4], bfr[4][4];
#pragma unroll
            for (int mi = 0; mi < 4; ++mi)
                ldsm_x4(af[mi], stA + swz((aRow + mi * 16) * ROWB + aCol + ks * 32));
#pragma unroll
            for (int g = 0; g < 4; ++g)
                ldsm_x4(bfr[g], stB + swz((bRow + g * 16) * ROWB + bCol + ks * 32));
#pragma unroll
            for (int mi = 0; mi < 4; ++mi)
#pragma unroll
                for (int ni = 0; ni < 8; ++ni)
                    mma_f16(acc[mi][ni], af[mi], &bfr[ni >> 1][(ni & 1) * 2]);
        }

        if (c + 2 < NCH) {
            __syncthreads();          // all warps done reading buf c&1
            load_stage(c & 1, c + 2); // refill it
        }
    }
    __syncthreads();

    // Epilogue: unpack f16 acc, masked min/max with ordered-uint atomics.
    const int lq = lane >> 2;
    const int lr = (lane & 3) * 2;
#pragma unroll
    for (int mi = 0; mi < 4; ++mi) {
#pragma unroll
        for (int h = 0; h < 2; ++h) {
            const int rloc = warp_m + mi * 16 + h * 8 + lq;
            const int tg = sT[rloc];
            const int ix = sI[rloc];
            float pmin = f_inf(), nmax = f_ninf();
#pragma unroll
            for (int ni = 0; ni < 8; ++ni) {
                const float2 f2 = __half22float2(
                    *reinterpret_cast<const __half2*>(&acc[mi][ni][h]));
#pragma unroll
                for (int j = 0; j < 2; ++j) {
                    const int cloc = warp_n + ni * 8 + lr + j;
                    const float v = (j == 0) ? f2.x : f2.y;
                    if (sLab[cloc] == tg) {
                        if (colBase + cloc != ix) pmin = fminf(pmin, v);
                    } else {
                        nmax = fmaxf(nmax, v);
                    }
                }
            }
            if (pmin <  f_inf())  atomicMin(&sPosU[rloc], encOrd(pmin));
            if (nmax > f_ninf())  atomicMax(&sNegU[rloc], encOrd(nmax));
        }
    }
    __syncthreads();

    if (tid < BM) {
        const unsigned p = sPosU[tid], q = sNegU[tid];
        if (p != 0xFFFFFFFFu) atomicMin(&g_posU[rowBase + tid], p);
        if (q != 0u)          atomicMax(&g_negU[rowBase + tid], q);
    }

    // ---- fused finale ----
    __threadfence();
    if (tid == 0) {
        const unsigned total = gridDim.x * gridDim.y;
        sIsLast = (atomicAdd(&g_ctr, 1u) == total - 1u);
    }
    __syncthreads();
    if (!sIsLast) return;

    __threadfence();
    float l = 0.f;
#pragma unroll
    for (int r = 0; r < 4; ++r) {
        const int row = tid + r * 256;
        const float pos = decOrd(__ldcg(&g_posU[row]));
        const float neg = decOrd(__ldcg(&g_negU[row]));
        l += fmaxf(neg - pos + MARGIN, 0.0f);
    }
#pragma unroll
    for (int o = 16; o > 0; o >>= 1) l += __shfl_xor_sync(0xffffffffu, l, o);
    if (lane == 0) sRed[wid] = l;
    __syncthreads();
    if (tid < 8) {
        float s = sRed[tid];
#pragma unroll
        for (int o = 4; o > 0; o >>= 1) s += __shfl_xor_sync(0xffu, s, o);
        if (tid == 0) {
            out[0] = s * (1.0f / (float)M);
            g_ctr = 0;
        }
    }
}

extern "C" void kernel_launch(void* const* d_in, const int* in_sizes, int n_in,
                              void* d_out, int out_size) {
    const float* A       = (const float*)d_in[0];
    const float* B       = (const float*)d_in[1];
    const int*   targets = (const int*)  d_in[2];
    const int*   idxv    = (const int*)  d_in[3];
    const int*   labels  = (const int*)  d_in[4];
    float*       out     = (float*)d_out;

    static bool attrSet = false;
    if (!attrSet) {
        cudaFuncSetAttribute(tl_gemm, cudaFuncAttributeMaxDynamicSharedMemorySize,
                             SMEM_TOTAL);
        attrSet = true;
    }

    void *pPos = nullptr, *pNeg = nullptr;
    cudaGetSymbolAddress(&pPos, g_posU);
    cudaGetSymbolAddress(&pNeg, g_negU);
    cudaMemsetAsync(pPos, 0xFF, M * sizeof(unsigned));
    cudaMemsetAsync(pNeg, 0x00, M * sizeof(unsigned));

    tl_quant<<<1024, 256>>>(A, B);
    dim3 grid(N / BN, M / BM);   // 128 x 8 = 1024 CTAs
    tl_gemm<<<grid, 256, SMEM_TOTAL>>>(targets, idxv, labels, out);
}

// round 12
// speedup vs baseline: 1.5522x; 1.0947x over previous
#include <cuda_runtime.h>
#include <cuda_fp16.h>
#include <cstdint>

constexpr int M = 1024;
constexpr int N = 32768;
constexpr int K = 512;
constexpr float MARGIN = 0.3f;

constexpr int BM = 128, BN = 256, BK = 64;
constexpr int NCH = K / BK;              // 8
constexpr int ROWB = 128;                // 64 f16 = 128B row, SW128 swizzle

// dynamic smem layout (double buffered, SW128)
constexpr uint32_t OFF_LAB = 0;                          // 256 ints = 1KB
constexpr uint32_t OFF_A   = 1024;
constexpr uint32_t A_STAGE = BM * ROWB;                  // 16384
constexpr uint32_t OFF_B   = OFF_A + 2 * A_STAGE;        // 33792
constexpr uint32_t B_STAGE = BN * ROWB;                  // 32768
constexpr uint32_t SMEM_TOTAL = OFF_B + 2 * B_STAGE;     // 99328 (x2 CTAs/SM)

__device__ unsigned g_posU[M];
__device__ unsigned g_negU[M];
__device__ unsigned g_ctr;
__device__ __half g_Ah[M * K];
__device__ __half g_Bh[(size_t)N * K];

__device__ __forceinline__ float f_inf()  { return __int_as_float(0x7f800000); }
__device__ __forceinline__ float f_ninf() { return __int_as_float(0xff800000); }

__device__ __forceinline__ unsigned encOrd(float f) {
    unsigned b = __float_as_uint(f);
    return (b & 0x80000000u) ? ~b : (b | 0x80000000u);
}
__device__ __forceinline__ float decOrd(unsigned u) {
    return (u & 0x80000000u) ? __uint_as_float(u ^ 0x80000000u)
                             : __uint_as_float(~u);
}

__device__ __forceinline__ uint32_t swz(uint32_t b) { return b ^ ((b >> 3) & 0x70); }

__device__ __forceinline__ uint32_t smem_u32(const void* p) {
    uint32_t a;
    asm("{ .reg .u64 t; cvta.to.shared.u64 t, %1; cvt.u32.u64 %0, t; }" : "=r"(a) : "l"(p));
    return a;
}
__device__ __forceinline__ void ldsm_x4(uint32_t* r, uint32_t addr) {
    asm volatile("ldmatrix.sync.aligned.m8n8.x4.shared.b16 {%0,%1,%2,%3}, [%4];"
                 : "=r"(r[0]), "=r"(r[1]), "=r"(r[2]), "=r"(r[3]) : "r"(addr));
}
__device__ __forceinline__ void mma_f16(uint32_t* d, const uint32_t* a, const uint32_t* b) {
    asm volatile(
        "mma.sync.aligned.m16n8k16.row.col.f16.f16.f16.f16 "
        "{%0,%1}, {%2,%3,%4,%5}, {%6,%7}, {%0,%1};"
        : "+r"(d[0]), "+r"(d[1])
        : "r"(a[0]), "r"(a[1]), "r"(a[2]), "r"(a[3]), "r"(b[0]), "r"(b[1]));
}
__device__ __forceinline__ void cp_async16(uint32_t dst, const void* src) {
    asm volatile("cp.async.cg.shared.global [%0], [%1], 16;" :: "r"(dst), "l"(src));
}
__device__ __forceinline__ void cp_commit() {
    asm volatile("cp.async.commit_group;" ::: "memory");
}
template <int NG> __device__ __forceinline__ void cp_wait() {
    asm volatile("cp.async.wait_group %0;" :: "n"(NG) : "memory");
}

// fp32 -> f16 scratch (streaming), plus min/max array init. 8 elems/iter.
__global__ void tl_quant(const float* __restrict__ A, const float* __restrict__ B) {
    const int gid = blockIdx.x * blockDim.x + threadIdx.x;
    const int nth = gridDim.x * blockDim.x;
    if (gid < M) { g_posU[gid] = 0xFFFFFFFFu; g_negU[gid] = 0u; }

    auto pack8 = [](float4 a, float4 b) {
        __half2 h0 = __floats2half2_rn(a.x, a.y);
        __half2 h1 = __floats2half2_rn(a.z, a.w);
        __half2 h2 = __floats2half2_rn(b.x, b.y);
        __half2 h3 = __floats2half2_rn(b.z, b.w);
        return make_uint4(*(uint32_t*)&h0, *(uint32_t*)&h1,
                          *(uint32_t*)&h2, *(uint32_t*)&h3);
    };

    for (int i = gid; i < M * K / 8; i += nth) {
        const float4* src = reinterpret_cast<const float4*>(A) + 2 * (size_t)i;
        float4 v0 = __ldcs(src), v1 = __ldcs(src + 1);
        __stcs(reinterpret_cast<uint4*>(g_Ah) + i, pack8(v0, v1));
    }
#pragma unroll 4
    for (size_t i = gid; i < (size_t)N * K / 8; i += nth) {
        const float4* src = reinterpret_cast<const float4*>(B) + 2 * i;
        float4 v0 = __ldcs(src), v1 = __ldcs(src + 1);
        __stcs(reinterpret_cast<uint4*>(g_Bh) + i, pack8(v0, v1));
    }
}

__global__ __launch_bounds__(256, 2)
void tl_gemm(const int* __restrict__ targets, const int* __restrict__ idxv,
             const int* __restrict__ labels, float* __restrict__ out)
{
    extern __shared__ __align__(1024) char smem[];
    __shared__ int      sT[BM];
    __shared__ int      sI[BM];
    __shared__ unsigned sPosU[BM];
    __shared__ unsigned sNegU[BM];
    __shared__ float    sRed[8];
    __shared__ unsigned sIsLast;

    const uint32_t sb = smem_u32(smem);
    const uint32_t sA = sb + OFF_A;
    const uint32_t sB = sb + OFF_B;
    int* sLab = (int*)(smem + OFF_LAB);

    const int tid  = threadIdx.x;
    const int lane = tid & 31;
    const int wid  = tid >> 5;
    const int rowBase = blockIdx.y * BM;
    const int colBase = blockIdx.x * BN;

    // 8 warps: 2 (m) x 4 (n); warp tile 64 x 64
    const int warp_m = (wid >> 2) * 64;
    const int warp_n = (wid & 3) * 64;

    for (int i = tid; i < BN; i += 256) sLab[i] = labels[colBase + i];
    if (tid < BM) {
        sT[tid] = targets[rowBase + tid];
        sI[tid] = idxv[rowBase + tid];
        sPosU[tid] = 0xFFFFFFFFu;
        sNegU[tid] = 0u;
    }

    auto load_stage = [&](int st, int c) {
        const int kb = c * BK;
        const uint32_t dA = sA + st * A_STAGE;
        const uint32_t dB = sB + st * B_STAGE;
#pragma unroll
        for (int i = 0; i < 4; ++i) {
            const int v = tid + i * 256;
            const int r = v >> 3, q = v & 7;
            cp_async16(dA + swz((uint32_t)(r * ROWB + q * 16)),
                       g_Ah + (size_t)(rowBase + r) * K + kb + q * 8);
        }
#pragma unroll
        for (int i = 0; i < 8; ++i) {
            const int v = tid + i * 256;
            const int r = v >> 3, q = v & 7;
            cp_async16(dB + swz((uint32_t)(r * ROWB + q * 16)),
                       g_Bh + (size_t)(colBase + r) * K + kb + q * 8);
        }
        cp_commit();
    };

    // Hoisted, pre-swizzled ldmatrix base addresses.
    // Identity: swz(base + ks*32) == swz(base) ^ (ks<<5)   (col bits 4..6 disjoint)
    uint32_t aB[4], bB[4];
#pragma unroll
    for (int mi = 0; mi < 4; ++mi)
        aB[mi] = swz((uint32_t)(warp_m + (lane & 15) + mi * 16) * ROWB
                     + (lane >> 4) * 16);
#pragma unroll
    for (int g = 0; g < 4; ++g)
        bB[g] = swz((uint32_t)(warp_n + (lane & 7) + ((lane >> 4) & 1) * 8 + g * 16) * ROWB
                    + ((lane >> 3) & 1) * 16);

    uint32_t acc[4][8][2] = {};   // f16x2 accumulators

    load_stage(0, 0);
    load_stage(1, 1);

#pragma unroll 1
    for (int c = 0; c < NCH; ++c) {
        if (c + 1 < NCH) cp_wait<1>(); else cp_wait<0>();
        __syncthreads();

        const uint32_t stA = sA + (c & 1) * A_STAGE;
        const uint32_t stB = sB + (c & 1) * B_STAGE;
#pragma unroll
        for (int ks = 0; ks < 4; ++ks) {
            const uint32_t kx = (uint32_t)ks << 5;
            uint32_t af[4][4], bfr[4][4];
#pragma unroll
            for (int mi = 0; mi < 4; ++mi)
                ldsm_x4(af[mi], stA + (aB[mi] ^ kx));
#pragma unroll
            for (int g = 0; g < 4; ++g)
                ldsm_x4(bfr[g], stB + (bB[g] ^ kx));
#pragma unroll
            for (int mi = 0; mi < 4; ++mi)
#pragma unroll
                for (int ni = 0; ni < 8; ++ni)
                    mma_f16(acc[mi][ni], af[mi], &bfr[ni >> 1][(ni & 1) * 2]);
        }

        if (c + 2 < NCH) {
            __syncthreads();          // all warps done reading buf c&1
            load_stage(c & 1, c + 2); // refill it
        }
    }
    __syncthreads();

    // Epilogue: unpack f16 acc, masked min/max with ordered-uint atomics.
    const int lq = lane >> 2;
    const int lr = (lane & 3) * 2;
#pragma unroll
    for (int mi = 0; mi < 4; ++mi) {
#pragma unroll
        for (int h = 0; h < 2; ++h) {
            const int rloc = warp_m + mi * 16 + h * 8 + lq;
            const int tg = sT[rloc];
            const int ix = sI[rloc];
            float pmin = f_inf(), nmax = f_ninf();
#pragma unroll
            for (int ni = 0; ni < 8; ++ni) {
                const float2 f2 = __half22float2(
                    *reinterpret_cast<const __half2*>(&acc[mi][ni][h]));
#pragma unroll
                for (int j = 0; j < 2; ++j) {
                    const int cloc = warp_n + ni * 8 + lr + j;
                    const float v = (j == 0) ? f2.x : f2.y;
                    if (sLab[cloc] == tg) {
                        if (colBase + cloc != ix) pmin = fminf(pmin, v);
                    } else {
                        nmax = fmaxf(nmax, v);
                    }
                }
            }
            if (pmin <  f_inf())  atomicMin(&sPosU[rloc], encOrd(pmin));
            if (nmax > f_ninf())  atomicMax(&sNegU[rloc], encOrd(nmax));
        }
    }
    __syncthreads();

    if (tid < BM) {
        const unsigned p = sPosU[tid], q = sNegU[tid];
        if (p != 0xFFFFFFFFu) atomicMin(&g_posU[rowBase + tid], p);
        if (q != 0u)          atomicMax(&g_negU[rowBase + tid], q);
    }

    // ---- fused finale ----
    __threadfence();
    if (tid == 0) {
        const unsigned total = gridDim.x * gridDim.y;
        sIsLast = (atomicAdd(&g_ctr, 1u) == total - 1u);
    }
    __syncthreads();
    if (!sIsLast) return;

    __threadfence();
    float l = 0.f;
#pragma unroll
    for (int r = 0; r < 4; ++r) {
        const int row = tid + r * 256;
        const float pos = decOrd(__ldcg(&g_posU[row]));
        const float neg = decOrd(__ldcg(&g_negU[row]));
        l += fmaxf(neg - pos + MARGIN, 0.0f);
    }
#pragma unroll
    for (int o = 16; o > 0; o >>= 1) l += __shfl_xor_sync(0xffffffffu, l, o);
    if (lane == 0) sRed[wid] = l;
    __syncthreads();
    if (tid < 8) {
        float s = sRed[tid];
#pragma unroll
        for (int o = 4; o > 0; o >>= 1) s += __shfl_xor_sync(0xffu, s, o);
        if (tid == 0) {
            out[0] = s * (1.0f / (float)M);
            g_ctr = 0;
        }
    }
}

extern "C" void kernel_launch(void* const* d_in, const int* in_sizes, int n_in,
                              void* d_out, int out_size) {
    const float* A       = (const float*)d_in[0];
    const float* B       = (const float*)d_in[1];
    const int*   targets = (const int*)  d_in[2];
    const int*   idxv    = (const int*)  d_in[3];
    const int*   labels  = (const int*)  d_in[4];
    float*       out     = (float*)d_out;

    static bool attrSet = false;
    if (!attrSet) {
        cudaFuncSetAttribute(tl_gemm, cudaFuncAttributeMaxDynamicSharedMemorySize,
                             SMEM_TOTAL);
        attrSet = true;
    }

    tl_quant<<<1024, 256>>>(A, B);
    dim3 grid(N / BN, M / BM);   // 128 x 8 = 1024 CTAs
    tl_gemm<<<grid, 256, SMEM_TOTAL>>>(targets, idxv, labels, out);
}